// round 13
// baseline (speedup 1.0000x reference)
#include <cuda_runtime.h>
#include <cuda_bf16.h>
#include <cstdint>

typedef unsigned int u32;

#define LSEQ 2048
#define DIMV 32
#define CHK 64
#define NCHC 8                      // chunks per CTA (k-split 4)
#define KSPLIT 4
#define THREADS 256
#define NPAIRS 496
#define OUTW 528

#define STAGE 16384                 // A tile (8KB) + B tile (8KB)
#define BOFF 8192
#define SMEMSZ (2 * STAGE)          // 32768

// partial combined C32 per (batch, ksplit): [B*4][32*32] f32 = 8 MB
__device__ float g_part[512 * KSPLIT * 1024];

__device__ __forceinline__ u32 smem_u32(const void* p) {
    u32 a;
    asm("{ .reg .u64 t; cvta.to.shared.u64 t, %1; cvt.u32.u64 %0, t; }" : "=r"(a) : "l"(p));
    return a;
}
__device__ __forceinline__ u32 cvtpack(float lo, float hi) {   // low half = lo
    u32 r;
    asm("cvt.rn.bf16x2.f32 %0, %1, %2;" : "=r"(r) : "f"(hi), "f"(lo));
    return r;
}
__device__ __forceinline__ void sts128(u32 a, u32 x0, u32 x1, u32 x2, u32 x3) {
    asm volatile("st.shared.v4.b32 [%0], {%1,%2,%3,%4};"
                 ::"r"(a), "r"(x0), "r"(x1), "r"(x2), "r"(x3));
}
__device__ __forceinline__ void ldsm4(u32 addr, u32* r) {
    asm volatile("ldmatrix.sync.aligned.m8n8.x4.shared.b16 {%0,%1,%2,%3}, [%4];"
                 : "=r"(r[0]), "=r"(r[1]), "=r"(r[2]), "=r"(r[3]) : "r"(addr));
}
__device__ __forceinline__ void mma16816(float* d, const u32* a, u32 b0, u32 b1) {
    asm volatile(
        "mma.sync.aligned.m16n8k16.row.col.f32.bf16.bf16.f32 "
        "{%0,%1,%2,%3}, {%4,%5,%6,%7}, {%8,%9}, {%0,%1,%2,%3};"
        : "+f"(d[0]), "+f"(d[1]), "+f"(d[2]), "+f"(d[3])
        : "r"(a[0]), "r"(a[1]), "r"(a[2]), "r"(a[3]), "r"(b0), "r"(b1));
}

__global__ __launch_bounds__(THREADS, 3) void logsig_part(const float* __restrict__ x) {
    __shared__ __align__(128) char smem[SMEMSZ];

    const int b = blockIdx.x >> 2, ks = blockIdx.x & 3;
    const int tid = threadIdx.x, w = tid >> 5, lane = tid & 31;
    const int mh = w & 1, nh = (w >> 1) & 1, kh = w >> 2;   // warp = (m-half, n-half, k-half)
    const int c0 = ks * NCHC;
    const float* gx = x + (size_t)b * LSEQ * DIMV;
    const u32 sbase = smem_u32(smem);

    // direct-LDG chunk load: thread (w,lane) -> dim=lane, rows 8w..8w+8 of chunk c
    auto load9 = [&](float* v, int c) {
        const float* p = gx + (size_t)(c * CHK + 8 * w) * DIMV + lane;
#pragma unroll
        for (int j = 0; j < 9; j++) {
            bool ok = (c * CHK + 8 * w + j) < LSEQ;          // only global row 2048 fails
            v[j] = ok ? __ldg(p + j * DIMV) : 0.0f;
        }
    };

    // STS bases (swizzled 16B units; unit index = w within a 128B row)
    const u32 ust = (u32)((w ^ (lane & 7)) << 4);
    const u32 stA = sbase + (u32)lane * 128u + ust;

    float acc[8][4];
#pragma unroll
    for (int i = 0; i < 8; i++)
#pragma unroll
        for (int r = 0; r < 4; r++) acc[i][r] = 0.f;

    float vA[9], vB[9];
    load9(vA, c0);

    auto iter = [&](int cc, float* vc, float* vn) {
        const int c = c0 + cc;
        const u32 buf = (u32)(cc & 1) * STAGE;

        // ---- convert: 9 f32 -> bf16 hi/lo, 4x STS.128 into buf ----
        {
            float res[9];
            u32 h2[9];
#pragma unroll
            for (int j = 0; j < 9; j++) {
                h2[j] = cvtpack(vc[j], vc[j]);               // both halves = bf16(v)
                res[j] = vc[j] - __uint_as_float(h2[j] & 0xFFFF0000u);
            }
            u32 ah[4], al[4], bh[4], bl[4];
#pragma unroll
            for (int i = 0; i < 4; i++) {
                ah[i] = __byte_perm(h2[2 * i], h2[2 * i + 1], 0x7632);
                al[i] = cvtpack(res[2 * i], res[2 * i + 1]);
                bh[i] = __byte_perm(h2[2 * i + 1], h2[2 * i + 2], 0x7632);
                bl[i] = cvtpack(res[2 * i + 1], res[2 * i + 2]);
            }
            sts128(stA + buf, ah[0], ah[1], ah[2], ah[3]);            // A hi (row d)
            sts128(stA + buf + 4096u, al[0], al[1], al[2], al[3]);    // A lo (row d+32)
            sts128(stA + buf + BOFF, bh[0], bh[1], bh[2], bh[3]);     // B hi
            sts128(stA + buf + BOFF + 4096u, bl[0], bl[1], bl[2], bl[3]);
        }

        if (cc + 1 < NCHC) load9(vn, c + 1);  // prefetch next chunk (covered by mma phase)

        __syncthreads();                      // STS(c) visible; fences ldsm(c-1) vs STS(c+1)

        // ---- ldmatrix + mma: this warp's k-half (2 k16 blocks) ----
        const int rla = lane & 15, khl = lane >> 4;
#pragma unroll
        for (int qi = 0; qi < 2; qi++) {
            const u32 u = (u32)((kh * 2 + qi) * 2 + khl);
            u32 afr[2][4], bfr[2][4];
#pragma unroll
            for (int tm = 0; tm < 2; tm++) {
                u32 row = (u32)(mh * 32 + tm * 16 + rla);
                ldsm4(sbase + buf + row * 128u + ((u ^ (row & 7u)) << 4), afr[tm]);
            }
#pragma unroll
            for (int tn = 0; tn < 2; tn++) {
                u32 row = (u32)(nh * 32 + tn * 16 + rla);
                ldsm4(sbase + buf + BOFF + row * 128u + ((u ^ (row & 7u)) << 4), bfr[tn]);
            }
#pragma unroll
            for (int tm = 0; tm < 2; tm++)
#pragma unroll
                for (int tn = 0; tn < 2; tn++) {
                    mma16816(acc[tm * 4 + tn * 2 + 0], afr[tm], bfr[tn][0], bfr[tn][2]);
                    mma16816(acc[tm * 4 + tn * 2 + 1], afr[tm], bfr[tn][1], bfr[tn][3]);
                }
        }
    };

#pragma unroll 1
    for (int cc = 0; cc < NCHC; cc += 2) {
        iter(cc, vA, vB);
        iter(cc + 1, vB, vA);
    }

    __syncthreads();
    // ---- k-half reduction into smem C[64][66] ----
    float* C = (float*)smem;
    if (kh == 0) {
#pragma unroll
        for (int t = 0; t < 8; t++) {
            int tm = t >> 2, tn8 = t & 3;
#pragma unroll
            for (int r = 0; r < 4; r++) {
                int m = mh * 32 + tm * 16 + (lane >> 2) + (r >> 1) * 8;
                int n = nh * 32 + tn8 * 8 + (lane & 3) * 2 + (r & 1);
                C[m * 66 + n] = acc[t][r];
            }
        }
    }
    __syncthreads();
    if (kh == 1) {
#pragma unroll
        for (int t = 0; t < 8; t++) {
            int tm = t >> 2, tn8 = t & 3;
#pragma unroll
            for (int r = 0; r < 4; r++) {
                int m = mh * 32 + tm * 16 + (lane >> 2) + (r >> 1) * 8;
                int n = nh * 32 + tn8 * 8 + (lane & 3) * 2 + (r & 1);
                C[m * 66 + n] += acc[t][r];
            }
        }
    }
    __syncthreads();

    // ---- combine 4 hi/lo blocks -> 32x32 partial, write to g_part ----
#pragma unroll
    for (int q = tid; q < 1024; q += THREADS) {
        int i = q >> 5, j = q & 31;
        float v = C[i * 66 + j] + C[i * 66 + j + 32]
                + C[(i + 32) * 66 + j] + C[(i + 32) * 66 + j + 32];
        g_part[(size_t)blockIdx.x * 1024 + q] = v;
    }
}

// ---------------- kernel 2: combine + outputs (proven, 7.0 us) ----------------
__global__ __launch_bounds__(THREADS) void logsig_final(const float* __restrict__ x,
                                                        float* __restrict__ out) {
    const int b = blockIdx.x;
    const int tid = threadIdx.x;

    __shared__ float Cs[1024];
    __shared__ float x0s[DIMV];
    __shared__ float l1s[DIMV];

    const int e0 = tid * 4;
    float4 sum = make_float4(0.f, 0.f, 0.f, 0.f);
#pragma unroll
    for (int s = 0; s < KSPLIT; s++) {
        float4 v = *(const float4*)&g_part[((size_t)b * KSPLIT + s) * 1024 + e0];
        sum.x += v.x; sum.y += v.y; sum.z += v.z; sum.w += v.w;
    }
    *(float4*)&Cs[e0] = sum;

    if (tid < DIMV) {
        float x0 = x[(size_t)b * LSEQ * DIMV + tid];
        float xl = x[(size_t)b * LSEQ * DIMV + (size_t)(LSEQ - 1) * DIMV + tid];
        float l1 = xl - x0;
        x0s[tid] = x0;
        l1s[tid] = l1;
        out[(size_t)b * OUTW + tid] = l1;
    }
    __syncthreads();

#pragma unroll
    for (int p = tid; p < NPAIRS; p += THREADS) {
        float f = (63.0f - sqrtf((float)(3969 - 8 * p))) * 0.5f;
        int i = (int)f;
        int base = i * (63 - i) / 2;
        if (base > p) { i--; base = i * (63 - i) / 2; }
        else { int nb = (i + 1) * (62 - i) / 2; if (nb <= p) { i++; base = nb; } }
        int j = i + 1 + (p - base);
        float val = 0.5f * ((Cs[i * 32 + j] - Cs[j * 32 + i])
                            - x0s[i] * l1s[j] + x0s[j] * l1s[i]);
        out[(size_t)b * OUTW + DIMV + p] = val;
    }
}

extern "C" void kernel_launch(void* const* d_in, const int* in_sizes, int n_in,
                              void* d_out, int out_size) {
    const float* x = (const float*)d_in[0];
    float* out = (float*)d_out;
    const int B = in_sizes[0] / (LSEQ * DIMV);   // 512
    logsig_part<<<B * KSPLIT, THREADS>>>(x);
    logsig_final<<<B, THREADS>>>(x, out);
}

// round 14
// speedup vs baseline: 1.0673x; 1.0673x over previous
#include <cuda_runtime.h>
#include <cuda_bf16.h>
#include <cstdint>

typedef unsigned int u32;

#define LSEQ 2048
#define DIMV 32
#define CHK 64
#define NCH 32
#define THREADS 256
#define NPAIRS 496
#define OUTW 528

#define STAGE 16384                 // A tile (8KB) + B tile (8KB)
#define BOFF 8192
#define SMEMSZ (2 * STAGE)          // 32768

__device__ __forceinline__ u32 smem_u32(const void* p) {
    u32 a;
    asm("{ .reg .u64 t; cvta.to.shared.u64 t, %1; cvt.u32.u64 %0, t; }" : "=r"(a) : "l"(p));
    return a;
}
__device__ __forceinline__ u32 cvtpack(float lo, float hi) {   // low half = lo
    u32 r;
    asm("cvt.rn.bf16x2.f32 %0, %1, %2;" : "=r"(r) : "f"(hi), "f"(lo));
    return r;
}
__device__ __forceinline__ void sts128(u32 a, u32 x0, u32 x1, u32 x2, u32 x3) {
    asm volatile("st.shared.v4.b32 [%0], {%1,%2,%3,%4};"
                 ::"r"(a), "r"(x0), "r"(x1), "r"(x2), "r"(x3));
}
__device__ __forceinline__ void ldsm4(u32 addr, u32* r) {
    asm volatile("ldmatrix.sync.aligned.m8n8.x4.shared.b16 {%0,%1,%2,%3}, [%4];"
                 : "=r"(r[0]), "=r"(r[1]), "=r"(r[2]), "=r"(r[3]) : "r"(addr));
}
__device__ __forceinline__ void mma16816(float* d, const u32* a, u32 b0, u32 b1) {
    asm volatile(
        "mma.sync.aligned.m16n8k16.row.col.f32.bf16.bf16.f32 "
        "{%0,%1,%2,%3}, {%4,%5,%6,%7}, {%8,%9}, {%0,%1,%2,%3};"
        : "+f"(d[0]), "+f"(d[1]), "+f"(d[2]), "+f"(d[3])
        : "r"(a[0]), "r"(a[1]), "r"(a[2]), "r"(a[3]), "r"(b0), "r"(b1));
}

__global__ __launch_bounds__(THREADS, 4) void logsig_mma(const float* __restrict__ x,
                                                         float* __restrict__ out) {
    __shared__ __align__(128) char smem[SMEMSZ];
    __shared__ float x0s[DIMV], l1s[DIMV];

    const int b = blockIdx.x, tid = threadIdx.x, w = tid >> 5, lane = tid & 31;
    const int mh = w & 1, nh = (w >> 1) & 1, kh = w >> 2;   // warp = (m-half, n-half, k-half)
    const float* gx = x + (size_t)b * LSEQ * DIMV;
    const u32 sbase = smem_u32(smem);

    // STS bases (swizzled 16B units; unit index = w within a 128B row)
    const u32 ust = (u32)((w ^ (lane & 7)) << 4);
    const u32 stA = sbase + (u32)lane * 128u + ust;

    float acc[8][4];
#pragma unroll
    for (int i = 0; i < 8; i++)
#pragma unroll
        for (int r = 0; r < 4; r++) acc[i][r] = 0.f;

#pragma unroll 1
    for (int c = 0; c < NCH; c++) {
        const u32 buf = (u32)(c & 1) * STAGE;

        // ---- load 9 rows (this thread: dim=lane, rows 8w..8w+8 of chunk) ----
        float v[9];
        {
            const float* p = gx + (size_t)(c * CHK + 8 * w) * DIMV + lane;
#pragma unroll
            for (int j = 0; j < 9; j++) {
                bool ok = (c * CHK + 8 * w + j) < LSEQ;      // only global row 2048 fails
                v[j] = ok ? __ldg(p + j * DIMV) : 0.0f;
            }
        }

        // ---- convert: 9 f32 -> bf16 hi/lo, 4x STS.128 into buf ----
        {
            float res[9];
            u32 h2[9];
#pragma unroll
            for (int j = 0; j < 9; j++) {
                h2[j] = cvtpack(v[j], v[j]);                 // both halves = bf16(v)
                res[j] = v[j] - __uint_as_float(h2[j] & 0xFFFF0000u);
            }
            u32 ah[4], al[4], bh[4], bl[4];
#pragma unroll
            for (int i = 0; i < 4; i++) {
                ah[i] = __byte_perm(h2[2 * i], h2[2 * i + 1], 0x7632);
                al[i] = cvtpack(res[2 * i], res[2 * i + 1]);
                bh[i] = __byte_perm(h2[2 * i + 1], h2[2 * i + 2], 0x7632);
                bl[i] = cvtpack(res[2 * i + 1], res[2 * i + 2]);
            }
            sts128(stA + buf, ah[0], ah[1], ah[2], ah[3]);            // A hi (row d)
            sts128(stA + buf + 4096u, al[0], al[1], al[2], al[3]);    // A lo (row d+32)
            sts128(stA + buf + BOFF, bh[0], bh[1], bh[2], bh[3]);     // B hi
            sts128(stA + buf + BOFF + 4096u, bl[0], bl[1], bl[2], bl[3]);
        }

        __syncthreads();                      // STS(c) visible; fences ldsm(c-1) vs STS(c+1)

        // ---- ldmatrix + mma: this warp's k-half (2 k16 blocks) ----
        const int rla = lane & 15, khl = lane >> 4;
#pragma unroll
        for (int qi = 0; qi < 2; qi++) {
            const u32 u = (u32)((kh * 2 + qi) * 2 + khl);
            u32 afr[2][4], bfr[2][4];
#pragma unroll
            for (int tm = 0; tm < 2; tm++) {
                u32 row = (u32)(mh * 32 + tm * 16 + rla);
                ldsm4(sbase + buf + row * 128u + ((u ^ (row & 7u)) << 4), afr[tm]);
            }
#pragma unroll
            for (int tn = 0; tn < 2; tn++) {
                u32 row = (u32)(nh * 32 + tn * 16 + rla);
                ldsm4(sbase + buf + BOFF + row * 128u + ((u ^ (row & 7u)) << 4), bfr[tn]);
            }
#pragma unroll
            for (int tm = 0; tm < 2; tm++)
#pragma unroll
                for (int tn = 0; tn < 2; tn++) {
                    mma16816(acc[tm * 4 + tn * 2 + 0], afr[tm], bfr[tn][0], bfr[tn][2]);
                    mma16816(acc[tm * 4 + tn * 2 + 1], afr[tm], bfr[tn][1], bfr[tn][3]);
                }
        }
    }

    __syncthreads();
    // ---- k-half reduction into smem C[64][66] (reuses tile region) ----
    float* C = (float*)smem;
    if (kh == 0) {
#pragma unroll
        for (int t = 0; t < 8; t++) {
            int tm = t >> 2, tn8 = t & 3;
#pragma unroll
            for (int r = 0; r < 4; r++) {
                int m = mh * 32 + tm * 16 + (lane >> 2) + (r >> 1) * 8;
                int n = nh * 32 + tn8 * 8 + (lane & 3) * 2 + (r & 1);
                C[m * 66 + n] = acc[t][r];
            }
        }
    }
    __syncthreads();
    if (kh == 1) {
#pragma unroll
        for (int t = 0; t < 8; t++) {
            int tm = t >> 2, tn8 = t & 3;
#pragma unroll
            for (int r = 0; r < 4; r++) {
                int m = mh * 32 + tm * 16 + (lane >> 2) + (r >> 1) * 8;
                int n = nh * 32 + tn8 * 8 + (lane & 3) * 2 + (r & 1);
                C[m * 66 + n] += acc[t][r];
            }
        }
    }
    if (tid < DIMV) {
        float x0 = gx[tid];
        float l1 = gx[(size_t)(LSEQ - 1) * DIMV + tid] - x0;
        x0s[tid] = x0;
        l1s[tid] = l1;
        out[(size_t)b * OUTW + tid] = l1;                    // level1
    }
    __syncthreads();

    // ---- areas: combine hi/lo blocks, antisymmetrize, correct, emit ----
#pragma unroll 1
    for (int p = tid; p < NPAIRS; p += THREADS) {
        float f = (63.0f - sqrtf((float)(3969 - 8 * p))) * 0.5f;
        int i = (int)f;
        int base = i * (63 - i) / 2;
        if (base > p) { i--; base = i * (63 - i) / 2; }
        else { int nb = (i + 1) * (62 - i) / 2; if (nb <= p) { i++; base = nb; } }
        int j = i + 1 + (p - base);
        float Cij = C[i * 66 + j] + C[i * 66 + j + 32]
                  + C[(i + 32) * 66 + j] + C[(i + 32) * 66 + j + 32];
        float Cji = C[j * 66 + i] + C[j * 66 + i + 32]
                  + C[(j + 32) * 66 + i] + C[(j + 32) * 66 + i + 32];
        out[(size_t)b * OUTW + DIMV + p] =
            0.5f * ((Cij - Cji) - x0s[i] * l1s[j] + x0s[j] * l1s[i]);
    }
}

extern "C" void kernel_launch(void* const* d_in, const int* in_sizes, int n_in,
                              void* d_out, int out_size) {
    const float* x = (const float*)d_in[0];
    float* out = (float*)d_out;
    const int B = in_sizes[0] / (LSEQ * DIMV);   // 512
    logsig_mma<<<B, THREADS>>>(x, out);
}